// round 15
// baseline (speedup 1.0000x reference)
#include <cuda_runtime.h>
#include <cuda_fp16.h>
#include <cstdint>

// Problem dims (fixed by setup_inputs)
#define N_ROWS 16384
#define D_DIM  768
#define P_DIM  2048
#define C_DIM  1000
#define C_PAD  1024

// Scratch (allocation-free: __device__ globals)
__device__ __half g_hn[(size_t)N_ROWS * D_DIM];   // normalized h, fp16
__device__ __half g_pn[(size_t)P_DIM  * D_DIM];   // normalized prototypes, fp16
__device__ __half g_act[(size_t)N_ROWS * P_DIM];  // activations, fp16
__device__ __half g_pct[(size_t)C_PAD  * P_DIM];  // prototype_class transposed+padded

// ---------------------------------------------------------------------------
// Row L2 normalize (vectorized): one block per row, fp32 in -> fp16 out.
// ---------------------------------------------------------------------------
__global__ void normalize_rows_kernel(const float* __restrict__ xh,
                                      const float* __restrict__ xp) {
    int row = blockIdx.x;
    const float* xr;
    __half* yr;
    if (row < N_ROWS) {
        xr = xh + (size_t)row * D_DIM;
        yr = g_hn + (size_t)row * D_DIM;
    } else {
        xr = xp + (size_t)(row - N_ROWS) * D_DIM;
        yr = g_pn + (size_t)(row - N_ROWS) * D_DIM;
    }
    int tid = threadIdx.x;
    float4 v = make_float4(0.f, 0.f, 0.f, 0.f);
    if (tid < 192) v = ((const float4*)xr)[tid];
    float ss = v.x * v.x + v.y * v.y + v.z * v.z + v.w * v.w;
    #pragma unroll
    for (int o = 16; o; o >>= 1) ss += __shfl_xor_sync(0xffffffff, ss, o);
    __shared__ float wsum[8];
    int w = tid >> 5, l = tid & 31;
    if (l == 0) wsum[w] = ss;
    __syncthreads();
    if (w == 0) {
        float s = (l < 8) ? wsum[l] : 0.f;
        #pragma unroll
        for (int o = 4; o; o >>= 1) s += __shfl_xor_sync(0xffffffff, s, o);
        if (l == 0) wsum[0] = s;
    }
    __syncthreads();
    float inv = 1.0f / fmaxf(sqrtf(wsum[0]), 1e-12f);
    if (tid < 192) {
        __half2 h0 = __floats2half2_rn(v.x * inv, v.y * inv);
        __half2 h1 = __floats2half2_rn(v.z * inv, v.w * inv);
        uint2 pack;
        pack.x = *(uint32_t*)&h0;
        pack.y = *(uint32_t*)&h1;
        ((uint2*)yr)[tid] = pack;
    }
}

// ---------------------------------------------------------------------------
// Transpose prototype_class [P, C] fp32 -> g_pct [C_PAD, P] fp16, zero-padded
// ---------------------------------------------------------------------------
__global__ void transpose_pc_kernel(const float* __restrict__ pc) {
    __shared__ float tile[32][33];
    int p0 = blockIdx.x * 32, c0 = blockIdx.y * 32;
    int tx = threadIdx.x, ty = threadIdx.y;   // block (32, 8)
    #pragma unroll
    for (int j = 0; j < 32; j += 8) {
        int p = p0 + ty + j, c = c0 + tx;
        tile[ty + j][tx] = (c < C_DIM) ? pc[(size_t)p * C_DIM + c] : 0.f;
    }
    __syncthreads();
    #pragma unroll
    for (int j = 0; j < 32; j += 8) {
        int c = c0 + ty + j, p = p0 + tx;
        g_pct[(size_t)c * P_DIM + p] = __float2half(tile[tx][ty + j]);
    }
}

// ---------------------------------------------------------------------------
// Common constants. Rows padded to 40 halfs (80B).
// GEMM1: CTA tile 128x128 (2x2 warps of 64x64), stage = A(128x32)+B(128x32).
// GEMM2: CTA tile 128x256 (2x4 warps of 64x64), stage = A(128x32)+B(256x32).
// ---------------------------------------------------------------------------
#define PADK 40
#define STAGE_HALFS (2 * 128 * PADK)            // GEMM1 stage (A+B 128 rows)
#define STAGE_BYTES (STAGE_HALFS * 2)
#define G1_STAGES 3
#define TILES_OFF 1024
#define G1_SMEM (TILES_OFF + G1_STAGES * STAGE_BYTES)   // 62464

#define G2_STAGES 5
#define STAGE2_HALFS ((128 + 256) * PADK)       // 15360 halfs = 30720 B
#define G2_SMEM (TILES_OFF + G2_STAGES * STAGE2_HALFS * 2)   // 154624

__device__ __forceinline__ uint32_t smem_u32(const void* p) {
    return (uint32_t)__cvta_generic_to_shared(p);
}

#define MBARRIER_INIT(addr, cnt) \
    asm volatile("mbarrier.init.shared.b64 [%0], %1;" :: "r"(addr), "r"(cnt) : "memory")
#define MBARRIER_ARRIVE(addr) \
    asm volatile("mbarrier.arrive.shared.b64 _, [%0];" :: "r"(addr) : "memory")
#define CPASYNC_MBAR_ARRIVE_NOINC(addr) \
    asm volatile("cp.async.mbarrier.arrive.noinc.shared.b64 [%0];" :: "r"(addr) : "memory")

#define MBARRIER_WAIT_PARITY(mbar, par) do {                                   \
    uint32_t _m = (mbar), _p = (par), _done;                                   \
    asm volatile("{\n\t.reg .pred p;\n\t"                                      \
        "mbarrier.try_wait.parity.shared.b64 p, [%1], %2;\n\t"                 \
        "selp.b32 %0, 1, 0, p;\n\t}" : "=r"(_done) : "r"(_m), "r"(_p) : "memory"); \
    if (!_done) {                                                              \
        asm volatile("{\n\t.reg .pred P1;\n\t"                                 \
            "WL_%=:\n\t"                                                       \
            "mbarrier.try_wait.parity.shared.b64 P1, [%0], %1;\n\t"            \
            "@P1 bra.uni WD_%=;\n\t"                                           \
            "bra.uni WL_%=;\n\t"                                               \
            "WD_%=:\n\t}" :: "r"(_m), "r"(_p) : "memory");                     \
    }                                                                          \
} while (0)

// Producer-warp load for GEMM1: A 128 rows + B 128 rows (16 iters x 2).
#define P_LOAD_TILE(gm, gn, kt, s)                                            \
    do {                                                                      \
        const __half* ga = A + (size_t)(gm) * KDIM + (kt) * 32;               \
        const __half* gb = B + (size_t)(gn) * KDIM + (kt) * 32;               \
        __half* sa_ = tiles + (size_t)(s) * STAGE_HALFS;                      \
        __half* sb_ = sa_ + 128 * PADK;                                       \
        _Pragma("unroll")                                                     \
        for (int i = 0; i < 16; ++i) {                                        \
            int l = lane + i * 32;                                            \
            int row = l >> 2, ch = l & 3;                                     \
            asm volatile("cp.async.cg.shared.global [%0], [%1], 16;\n"        \
                :: "r"(smem_u32(sa_ + row * PADK + ch * 8)),                  \
                   "l"(ga + (size_t)row * KDIM + ch * 8));                    \
            asm volatile("cp.async.cg.shared.global [%0], [%1], 16;\n"        \
                :: "r"(smem_u32(sb_ + row * PADK + ch * 8)),                  \
                   "l"(gb + (size_t)row * KDIM + ch * 8));                    \
        }                                                                     \
    } while (0)

// Producer-warp load for GEMM2: A 128 rows (16 iters) + B 256 rows (32 iters).
#define P_LOAD_TILE2(gm, gn, kt, s)                                           \
    do {                                                                      \
        const __half* ga = A + (size_t)(gm) * KDIM + (kt) * 32;               \
        const __half* gb = B + (size_t)(gn) * KDIM + (kt) * 32;               \
        __half* sa_ = tiles + (size_t)(s) * STAGE2_HALFS;                     \
        __half* sb_ = sa_ + 128 * PADK;                                       \
        _Pragma("unroll")                                                     \
        for (int i = 0; i < 16; ++i) {                                        \
            int l = lane + i * 32;                                            \
            int row = l >> 2, ch = l & 3;                                     \
            asm volatile("cp.async.cg.shared.global [%0], [%1], 16;\n"        \
                :: "r"(smem_u32(sa_ + row * PADK + ch * 8)),                  \
                   "l"(ga + (size_t)row * KDIM + ch * 8));                    \
        }                                                                     \
        _Pragma("unroll")                                                     \
        for (int i = 0; i < 32; ++i) {                                        \
            int l = lane + i * 32;                                            \
            int row = l >> 2, ch = l & 3;                                     \
            asm volatile("cp.async.cg.shared.global [%0], [%1], 16;\n"        \
                :: "r"(smem_u32(sb_ + row * PADK + ch * 8)),                  \
                   "l"(gb + (size_t)row * KDIM + ch * 8));                    \
        }                                                                     \
    } while (0)

#define LDSM_A(r, sa, f, ks)                                                  \
    do {                                                                      \
        int row_ = wm * 64 + (f) * 16 + (lane & 15);                          \
        int col_ = (ks) * 16 + (lane >> 4) * 8;                               \
        asm volatile(                                                         \
            "ldmatrix.sync.aligned.m8n8.x4.shared.b16 {%0,%1,%2,%3}, [%4];\n" \
            : "=r"((r)[0]), "=r"((r)[1]), "=r"((r)[2]), "=r"((r)[3])          \
            : "r"(smem_u32((sa) + row_ * PADK + col_)));                      \
    } while (0)

#define LDSM_B(r, sb, p, ks)                                                  \
    do {                                                                      \
        int row_ = wn * 64 + (p) * 16 + (lane & 7) + ((lane >> 4) << 3);      \
        int col_ = (ks) * 16 + ((lane >> 3) & 1) * 8;                         \
        asm volatile(                                                         \
            "ldmatrix.sync.aligned.m8n8.x4.shared.b16 {%0,%1,%2,%3}, [%4];\n" \
            : "=r"((r)[0]), "=r"((r)[1]), "=r"((r)[2]), "=r"((r)[3])          \
            : "r"(smem_u32((sb) + row_ * PADK + col_)));                      \
    } while (0)

#define HMMA_F32(c, a4, b0, b1)                                               \
    asm volatile(                                                             \
        "mma.sync.aligned.m16n8k16.row.col.f32.f16.f16.f32 "                  \
        "{%0,%1,%2,%3},{%4,%5,%6,%7},{%8,%9},{%0,%1,%2,%3};\n"                \
        : "+f"((c)[0]), "+f"((c)[1]), "+f"((c)[2]), "+f"((c)[3])              \
        : "r"((a4)[0]), "r"((a4)[1]), "r"((a4)[2]), "r"((a4)[3]),             \
          "r"(b0), "r"(b1))

#define HMMA_F16(c, a4, b0, b1)                                               \
    asm volatile(                                                             \
        "mma.sync.aligned.m16n8k16.row.col.f16.f16.f16.f16 "                  \
        "{%0,%1},{%2,%3,%4,%5},{%6,%7},{%0,%1};\n"                            \
        : "+r"((c)[0]), "+r"((c)[1])                                          \
        : "r"((a4)[0]), "r"((a4)[1]), "r"((a4)[2]), "r"((a4)[3]),             \
          "r"(b0), "r"(b1))

// ---------------------------------------------------------------------------
// GEMM1 (R13/R14 config, verbatim): f16 acc, 3 stages, 3 CTAs/SM, one-shot,
// warp-specialized producer (warp 4). act = exp(-tau*sqrt(max(2-2*dot,0))).
// ---------------------------------------------------------------------------
__global__ void __launch_bounds__(160, 3) gemm_act_kernel(
    const __half* __restrict__ A, const __half* __restrict__ B,
    __half* __restrict__ outH, const float* __restrict__ tempPtr)
{
    constexpr int KDIM = D_DIM;
    constexpr int KT = KDIM / 32;   // 24
    constexpr int S = G1_STAGES;
    extern __shared__ char smem[];
    const uint32_t sbar = smem_u32(smem);
    __half* tiles = (__half*)(smem + TILES_OFF);
    const int tid = threadIdx.x, wid = tid >> 5, lane = tid & 31;
    const int m0 = blockIdx.y * 128, n0 = blockIdx.x * 128;

    if (tid == 0) {
        #pragma unroll
        for (int s = 0; s < S; ++s) {
            MBARRIER_INIT(sbar + s * 16, 32);      // full: 32 producer lanes
            MBARRIER_INIT(sbar + s * 16 + 8, 4);   // empty: 4 consumer warps
        }
    }
    __syncthreads();

    if (wid == 4) {
        int st = 0, ph = 1;
        for (int kt = 0; kt < KT; ++kt) {
            MBARRIER_WAIT_PARITY(sbar + st * 16 + 8, ph);
            P_LOAD_TILE(m0, n0, kt, st);
            CPASYNC_MBAR_ARRIVE_NOINC(sbar + st * 16);
            if (++st == S) { st = 0; ph ^= 1; }
        }
        asm volatile("cp.async.wait_all;\n" ::: "memory");
        return;
    }

    const int wm = wid >> 1, wn = wid & 1;
    uint32_t acc[4][8][2];
    #pragma unroll
    for (int f = 0; f < 4; ++f)
        #pragma unroll
        for (int n = 0; n < 8; ++n) { acc[f][n][0] = 0u; acc[f][n][1] = 0u; }

    int st = 0, ph = 0;
    for (int kt = 0; kt < KT; ++kt) {
        MBARRIER_WAIT_PARITY(sbar + st * 16, ph);
        const __half* sa = tiles + (size_t)st * STAGE_HALFS;
        const __half* sb = sa + 128 * PADK;

        uint32_t a0[4][4], b0[4][4];
        #pragma unroll
        for (int f = 0; f < 4; ++f) LDSM_A(a0[f], sa, f, 0);
        #pragma unroll
        for (int p = 0; p < 4; ++p) LDSM_B(b0[p], sb, p, 0);
        #pragma unroll
        for (int f = 0; f < 4; ++f)
            #pragma unroll
            for (int nf = 0; nf < 8; ++nf)
                HMMA_F16(acc[f][nf], a0[f],
                         b0[nf >> 1][(nf & 1) * 2 + 0],
                         b0[nf >> 1][(nf & 1) * 2 + 1]);

        uint32_t a1[4][4], b1[4][4];
        #pragma unroll
        for (int f = 0; f < 4; ++f) LDSM_A(a1[f], sa, f, 1);
        #pragma unroll
        for (int p = 0; p < 4; ++p) LDSM_B(b1[p], sb, p, 1);
        if (lane == 0) MBARRIER_ARRIVE(sbar + st * 16 + 8);   // release stage
        #pragma unroll
        for (int f = 0; f < 4; ++f)
            #pragma unroll
            for (int nf = 0; nf < 8; ++nf)
                HMMA_F16(acc[f][nf], a1[f],
                         b1[nf >> 1][(nf & 1) * 2 + 0],
                         b1[nf >> 1][(nf & 1) * 2 + 1]);
        if (++st == S) { st = 0; ph ^= 1; }
    }

    float t = __ldg(tempPtr);
    float tau = (t > 20.f) ? t : log1pf(expf(t));   // softplus
    #pragma unroll
    for (int f = 0; f < 4; ++f)
        #pragma unroll
        for (int nf = 0; nf < 8; ++nf) {
            int row = m0 + wm * 64 + f * 16 + (lane >> 2);
            int col = n0 + wn * 64 + nf * 8 + (lane & 3) * 2;
            #pragma unroll
            for (int hh = 0; hh < 2; ++hh) {
                int r = row + hh * 8;
                float2 d = __half22float2(*(__half2*)&acc[f][nf][hh]);
                float a0e = __expf(-tau * sqrtf(fmaxf(2.f - 2.f * d.x, 0.f)));
                float a1e = __expf(-tau * sqrtf(fmaxf(2.f - 2.f * d.y, 0.f)));
                *(__half2*)(outH + (size_t)r * P_DIM + col) =
                    __floats2half2_rn(a0e, a1e);
            }
        }
}

// ---------------------------------------------------------------------------
// GEMM2: warp-specialized, f32 acc, tile 128x256 (8 consumer warps 2x4 +
// 1 producer warp, 288 thr, 1 CTA/SM => ~227 regs/thr budget), 5-stage
// mbarrier ring, persistent over 512 tiles with cursors carried across tiles.
// ---------------------------------------------------------------------------
#define G2_TILES ((N_ROWS / 128) * (C_PAD / 256))   // 512
#define G2_GRID  148

__global__ void __launch_bounds__(288, 1) gemm2_persistent_kernel(
    const __half* __restrict__ A, const __half* __restrict__ B,
    float* __restrict__ outF)
{
    constexpr int KDIM = P_DIM;
    constexpr int KT = KDIM / 32;   // 64
    constexpr int S = G2_STAGES;
    extern __shared__ char smem[];
    const uint32_t sbar = smem_u32(smem);
    __half* tiles = (__half*)(smem + TILES_OFF);
    const int tid = threadIdx.x, wid = tid >> 5, lane = tid & 31;

    if (tid == 0) {
        #pragma unroll
        for (int s = 0; s < S; ++s) {
            MBARRIER_INIT(sbar + s * 16, 32);      // full: producer lanes
            MBARRIER_INIT(sbar + s * 16 + 8, 8);   // empty: 8 consumer warps
        }
    }
    __syncthreads();

    if (wid == 8) {
        // ----------------- producer (persistent over tiles) -----------------
        int st = 0, ph = 1;
        for (int t = blockIdx.x; t < G2_TILES; t += G2_GRID) {
            const int m0 = (t >> 2) * 128, n0 = (t & 3) * 256;
            for (int kt = 0; kt < KT; ++kt) {
                MBARRIER_WAIT_PARITY(sbar + st * 16 + 8, ph);
                P_LOAD_TILE2(m0, n0, kt, st);
                CPASYNC_MBAR_ARRIVE_NOINC(sbar + st * 16);
                if (++st == S) { st = 0; ph ^= 1; }
            }
        }
        asm volatile("cp.async.wait_all;\n" ::: "memory");
        return;
    }

    // ----------------- consumers (wid 0..7, 2x4) -----------------
    const int wm = wid >> 2, wn = wid & 3;
    int st = 0, ph = 0;
    for (int t = blockIdx.x; t < G2_TILES; t += G2_GRID) {
        const int m0 = (t >> 2) * 128, n0 = (t & 3) * 256;

        float acc[4][8][4];
        #pragma unroll
        for (int f = 0; f < 4; ++f)
            #pragma unroll
            for (int n = 0; n < 8; ++n)
                #pragma unroll
                for (int k = 0; k < 4; ++k) acc[f][n][k] = 0.f;

        for (int kt = 0; kt < KT; ++kt) {
            MBARRIER_WAIT_PARITY(sbar + st * 16, ph);
            const __half* sa = tiles + (size_t)st * STAGE2_HALFS;
            const __half* sb = sa + 128 * PADK;

            uint32_t a0[4][4], b0[4][4];
            #pragma unroll
            for (int f = 0; f < 4; ++f) LDSM_A(a0[f], sa, f, 0);
            #pragma unroll
            for (int p = 0; p < 4; ++p) LDSM_B(b0[p], sb, p, 0);
            #pragma unroll
            for (int f = 0; f < 4; ++f)
                #pragma unroll
                for (int nf = 0; nf < 8; ++nf)
                    HMMA_F32(acc[f][nf], a0[f],
                             b0[nf >> 1][(nf & 1) * 2 + 0],
                             b0[nf >> 1][(nf & 1) * 2 + 1]);

            uint32_t a1[4][4], b1[4][4];
            #pragma unroll
            for (int f = 0; f < 4; ++f) LDSM_A(a1[f], sa, f, 1);
            #pragma unroll
            for (int p = 0; p < 4; ++p) LDSM_B(b1[p], sb, p, 1);
            if (lane == 0) MBARRIER_ARRIVE(sbar + st * 16 + 8);   // release
            #pragma unroll
            for (int f = 0; f < 4; ++f)
                #pragma unroll
                for (int nf = 0; nf < 8; ++nf)
                    HMMA_F32(acc[f][nf], a1[f],
                             b1[nf >> 1][(nf & 1) * 2 + 0],
                             b1[nf >> 1][(nf & 1) * 2 + 1]);
            if (++st == S) { st = 0; ph ^= 1; }
        }

        #pragma unroll
        for (int f = 0; f < 4; ++f)
            #pragma unroll
            for (int nf = 0; nf < 8; ++nf) {
                int row = m0 + wm * 64 + f * 16 + (lane >> 2);
                int col = n0 + wn * 64 + nf * 8 + (lane & 3) * 2;
                if (col < C_DIM) {   // even cols; pair never straddles C_DIM
                    #pragma unroll
                    for (int hh = 0; hh < 2; ++hh) {
                        int r = row + hh * 8;
                        float2 v = make_float2(acc[f][nf][hh * 2 + 0],
                                               acc[f][nf][hh * 2 + 1]);
                        *(float2*)(outF + (size_t)r * C_DIM + col) = v;
                    }
                }
            }
    }
}

// ---------------------------------------------------------------------------
// kernel_launch: 4 launches, all graph-capturable, no allocations.
// ---------------------------------------------------------------------------
extern "C" void kernel_launch(void* const* d_in, const int* in_sizes, int n_in,
                              void* d_out, int out_size) {
    const float* h    = (const float*)d_in[0];
    const float* prot = (const float*)d_in[1];
    const float* pc   = (const float*)d_in[2];
    const float* temp = (const float*)d_in[3];
    float* out = (float*)d_out;

    __half *hn = nullptr, *pn = nullptr, *act = nullptr, *pct = nullptr;
    cudaGetSymbolAddress((void**)&hn,  g_hn);
    cudaGetSymbolAddress((void**)&pn,  g_pn);
    cudaGetSymbolAddress((void**)&act, g_act);
    cudaGetSymbolAddress((void**)&pct, g_pct);

    cudaFuncSetAttribute(gemm_act_kernel,
                         cudaFuncAttributeMaxDynamicSharedMemorySize,
                         (int)G1_SMEM);
    cudaFuncSetAttribute(gemm2_persistent_kernel,
                         cudaFuncAttributeMaxDynamicSharedMemorySize,
                         (int)G2_SMEM);

    // 1) normalize h and prototypes -> fp16 (single launch, vectorized)
    normalize_rows_kernel<<<N_ROWS + P_DIM, 256>>>(h, prot);
    // 2) transpose + pad prototype_class -> fp16 [C_PAD, P]
    transpose_pc_kernel<<<dim3(P_DIM / 32, C_PAD / 32), dim3(32, 8)>>>(pc);
    // 3) GEMM1 (f16 accum, warp-specialized, 3 CTAs/SM) + dist/exp epilogue
    gemm_act_kernel
        <<<dim3(P_DIM / 128, N_ROWS / 128), 160, G1_SMEM>>>(hn, pn, act, temp);
    // 4) GEMM2 (f32 accum, warp-specialized 128x256, persistent, 1 CTA/SM)
    gemm2_persistent_kernel<<<G2_GRID, 288, G2_SMEM>>>(act, pct, out);
}

// round 16
// speedup vs baseline: 1.6605x; 1.6605x over previous
#include <cuda_runtime.h>
#include <cuda_fp16.h>
#include <cstdint>

// Problem dims (fixed by setup_inputs)
#define N_ROWS 16384
#define D_DIM  768
#define P_DIM  2048
#define C_DIM  1000
#define C_PAD  1024

// Scratch (allocation-free: __device__ globals)
__device__ __half g_hn[(size_t)N_ROWS * D_DIM];   // normalized h, fp16
__device__ __half g_pn[(size_t)P_DIM  * D_DIM];   // normalized prototypes, fp16
__device__ __half g_act[(size_t)N_ROWS * P_DIM];  // activations, fp16
__device__ __half g_pct[(size_t)C_PAD  * P_DIM];  // prototype_class transposed+padded

// ---------------------------------------------------------------------------
// Row L2 normalize (vectorized): one block per row, fp32 in -> fp16 out.
// ---------------------------------------------------------------------------
__global__ void normalize_rows_kernel(const float* __restrict__ xh,
                                      const float* __restrict__ xp) {
    int row = blockIdx.x;
    const float* xr;
    __half* yr;
    if (row < N_ROWS) {
        xr = xh + (size_t)row * D_DIM;
        yr = g_hn + (size_t)row * D_DIM;
    } else {
        xr = xp + (size_t)(row - N_ROWS) * D_DIM;
        yr = g_pn + (size_t)(row - N_ROWS) * D_DIM;
    }
    int tid = threadIdx.x;
    float4 v = make_float4(0.f, 0.f, 0.f, 0.f);
    if (tid < 192) v = ((const float4*)xr)[tid];
    float ss = v.x * v.x + v.y * v.y + v.z * v.z + v.w * v.w;
    #pragma unroll
    for (int o = 16; o; o >>= 1) ss += __shfl_xor_sync(0xffffffff, ss, o);
    __shared__ float wsum[8];
    int w = tid >> 5, l = tid & 31;
    if (l == 0) wsum[w] = ss;
    __syncthreads();
    if (w == 0) {
        float s = (l < 8) ? wsum[l] : 0.f;
        #pragma unroll
        for (int o = 4; o; o >>= 1) s += __shfl_xor_sync(0xffffffff, s, o);
        if (l == 0) wsum[0] = s;
    }
    __syncthreads();
    float inv = 1.0f / fmaxf(sqrtf(wsum[0]), 1e-12f);
    if (tid < 192) {
        __half2 h0 = __floats2half2_rn(v.x * inv, v.y * inv);
        __half2 h1 = __floats2half2_rn(v.z * inv, v.w * inv);
        uint2 pack;
        pack.x = *(uint32_t*)&h0;
        pack.y = *(uint32_t*)&h1;
        ((uint2*)yr)[tid] = pack;
    }
}

// ---------------------------------------------------------------------------
// Transpose prototype_class [P, C] fp32 -> g_pct [C_PAD, P] fp16, zero-padded
// ---------------------------------------------------------------------------
__global__ void transpose_pc_kernel(const float* __restrict__ pc) {
    __shared__ float tile[32][33];
    int p0 = blockIdx.x * 32, c0 = blockIdx.y * 32;
    int tx = threadIdx.x, ty = threadIdx.y;   // block (32, 8)
    #pragma unroll
    for (int j = 0; j < 32; j += 8) {
        int p = p0 + ty + j, c = c0 + tx;
        tile[ty + j][tx] = (c < C_DIM) ? pc[(size_t)p * C_DIM + c] : 0.f;
    }
    __syncthreads();
    #pragma unroll
    for (int j = 0; j < 32; j += 8) {
        int c = c0 + ty + j, p = p0 + tx;
        g_pct[(size_t)c * P_DIM + p] = __float2half(tile[tx][ty + j]);
    }
}

// ---------------------------------------------------------------------------
// Common constants. CTA tile 128x128x32 (2x2 warps of 64x64).
// Stage = A(128x32)+B(128x32), rows padded to 40 halfs.
// ---------------------------------------------------------------------------
#define PADK 40
#define STAGE_HALFS (2 * 128 * PADK)
#define STAGE_BYTES (STAGE_HALFS * 2)
#define G1_STAGES 3
#define G2_STAGES 4
#define TILES_OFF 1024
#define G1_SMEM (TILES_OFF + G1_STAGES * STAGE_BYTES)   // 62464
#define G2_SMEM (TILES_OFF + G2_STAGES * STAGE_BYTES)   // 82944

__device__ __forceinline__ uint32_t smem_u32(const void* p) {
    return (uint32_t)__cvta_generic_to_shared(p);
}

#define MBARRIER_INIT(addr, cnt) \
    asm volatile("mbarrier.init.shared.b64 [%0], %1;" :: "r"(addr), "r"(cnt) : "memory")
#define MBARRIER_ARRIVE(addr) \
    asm volatile("mbarrier.arrive.shared.b64 _, [%0];" :: "r"(addr) : "memory")
#define CPASYNC_MBAR_ARRIVE_NOINC(addr) \
    asm volatile("cp.async.mbarrier.arrive.noinc.shared.b64 [%0];" :: "r"(addr) : "memory")

#define MBARRIER_WAIT_PARITY(mbar, par) do {                                   \
    uint32_t _m = (mbar), _p = (par), _done;                                   \
    asm volatile("{\n\t.reg .pred p;\n\t"                                      \
        "mbarrier.try_wait.parity.shared.b64 p, [%1], %2;\n\t"                 \
        "selp.b32 %0, 1, 0, p;\n\t}" : "=r"(_done) : "r"(_m), "r"(_p) : "memory"); \
    if (!_done) {                                                              \
        asm volatile("{\n\t.reg .pred P1;\n\t"                                 \
            "WL_%=:\n\t"                                                       \
            "mbarrier.try_wait.parity.shared.b64 P1, [%0], %1;\n\t"            \
            "@P1 bra.uni WD_%=;\n\t"                                           \
            "bra.uni WL_%=;\n\t"                                               \
            "WD_%=:\n\t}" :: "r"(_m), "r"(_p) : "memory");                     \
    }                                                                          \
} while (0)

// Producer-warp load (GEMM1): 32 lanes, 16 iters x 2.
#define P_LOAD_TILE(gm, gn, kt, s)                                            \
    do {                                                                      \
        const __half* ga = A + (size_t)(gm) * KDIM + (kt) * 32;               \
        const __half* gb = B + (size_t)(gn) * KDIM + (kt) * 32;               \
        __half* sa_ = tiles + (size_t)(s) * STAGE_HALFS;                      \
        __half* sb_ = sa_ + 128 * PADK;                                       \
        _Pragma("unroll")                                                     \
        for (int i = 0; i < 16; ++i) {                                        \
            int l = lane + i * 32;                                            \
            int row = l >> 2, ch = l & 3;                                     \
            asm volatile("cp.async.cg.shared.global [%0], [%1], 16;\n"        \
                :: "r"(smem_u32(sa_ + row * PADK + ch * 8)),                  \
                   "l"(ga + (size_t)row * KDIM + ch * 8));                    \
            asm volatile("cp.async.cg.shared.global [%0], [%1], 16;\n"        \
                :: "r"(smem_u32(sb_ + row * PADK + ch * 8)),                  \
                   "l"(gb + (size_t)row * KDIM + ch * 8));                    \
        }                                                                     \
    } while (0)

// Block-wide load (GEMM2): 128 threads, 4 iters x 2, into `tiles` base.
#define LOAD_TILE_MB(gm, gn, kt, s)                                           \
    do {                                                                      \
        const __half* ga = A + (size_t)(gm) * KDIM + (kt) * 32;               \
        const __half* gb = B + (size_t)(gn) * KDIM + (kt) * 32;               \
        __half* sa_ = tiles + (size_t)(s) * STAGE_HALFS;                      \
        __half* sb_ = sa_ + 128 * PADK;                                       \
        _Pragma("unroll")                                                     \
        for (int i = 0; i < 4; ++i) {                                         \
            int l = tid + i * 128;                                            \
            int row = l >> 2, ch = l & 3;                                     \
            asm volatile("cp.async.cg.shared.global [%0], [%1], 16;\n"        \
                :: "r"(smem_u32(sa_ + row * PADK + ch * 8)),                  \
                   "l"(ga + (size_t)row * KDIM + ch * 8));                    \
            asm volatile("cp.async.cg.shared.global [%0], [%1], 16;\n"        \
                :: "r"(smem_u32(sb_ + row * PADK + ch * 8)),                  \
                   "l"(gb + (size_t)row * KDIM + ch * 8));                    \
        }                                                                     \
    } while (0)

#define LDSM_A(r, sa, f, ks)                                                  \
    do {                                                                      \
        int row_ = wm * 64 + (f) * 16 + (lane & 15);                          \
        int col_ = (ks) * 16 + (lane >> 4) * 8;                               \
        asm volatile(                                                         \
            "ldmatrix.sync.aligned.m8n8.x4.shared.b16 {%0,%1,%2,%3}, [%4];\n" \
            : "=r"((r)[0]), "=r"((r)[1]), "=r"((r)[2]), "=r"((r)[3])          \
            : "r"(smem_u32((sa) + row_ * PADK + col_)));                      \
    } while (0)

#define LDSM_B(r, sb, p, ks)                                                  \
    do {                                                                      \
        int row_ = wn * 64 + (p) * 16 + (lane & 7) + ((lane >> 4) << 3);      \
        int col_ = (ks) * 16 + ((lane >> 3) & 1) * 8;                         \
        asm volatile(                                                         \
            "ldmatrix.sync.aligned.m8n8.x4.shared.b16 {%0,%1,%2,%3}, [%4];\n" \
            : "=r"((r)[0]), "=r"((r)[1]), "=r"((r)[2]), "=r"((r)[3])          \
            : "r"(smem_u32((sb) + row_ * PADK + col_)));                      \
    } while (0)

#define HMMA_F32(c, a4, b0, b1)                                               \
    asm volatile(                                                             \
        "mma.sync.aligned.m16n8k16.row.col.f32.f16.f16.f32 "                  \
        "{%0,%1,%2,%3},{%4,%5,%6,%7},{%8,%9},{%0,%1,%2,%3};\n"                \
        : "+f"((c)[0]), "+f"((c)[1]), "+f"((c)[2]), "+f"((c)[3])              \
        : "r"((a4)[0]), "r"((a4)[1]), "r"((a4)[2]), "r"((a4)[3]),             \
          "r"(b0), "r"(b1))

#define HMMA_F16(c, a4, b0, b1)                                               \
    asm volatile(                                                             \
        "mma.sync.aligned.m16n8k16.row.col.f16.f16.f16.f16 "                  \
        "{%0,%1},{%2,%3,%4,%5},{%6,%7},{%0,%1};\n"                            \
        : "+r"((c)[0]), "+r"((c)[1])                                          \
        : "r"((a4)[0]), "r"((a4)[1]), "r"((a4)[2]), "r"((a4)[3]),             \
          "r"(b0), "r"(b1))

// ---------------------------------------------------------------------------
// GEMM1 (R14 config, verbatim): f16 acc, 3 stages, 3 CTAs/SM, one-shot,
// warp-specialized producer (warp 4). act = exp(-tau*sqrt(max(2-2*dot,0))).
// ---------------------------------------------------------------------------
__global__ void __launch_bounds__(160, 3) gemm_act_kernel(
    const __half* __restrict__ A, const __half* __restrict__ B,
    __half* __restrict__ outH, const float* __restrict__ tempPtr)
{
    constexpr int KDIM = D_DIM;
    constexpr int KT = KDIM / 32;   // 24
    constexpr int S = G1_STAGES;
    extern __shared__ char smem[];
    const uint32_t sbar = smem_u32(smem);
    __half* tiles = (__half*)(smem + TILES_OFF);
    const int tid = threadIdx.x, wid = tid >> 5, lane = tid & 31;
    const int m0 = blockIdx.y * 128, n0 = blockIdx.x * 128;

    if (tid == 0) {
        #pragma unroll
        for (int s = 0; s < S; ++s) {
            MBARRIER_INIT(sbar + s * 16, 32);      // full: 32 producer lanes
            MBARRIER_INIT(sbar + s * 16 + 8, 4);   // empty: 4 consumer warps
        }
    }
    __syncthreads();

    if (wid == 4) {
        int st = 0, ph = 1;
        for (int kt = 0; kt < KT; ++kt) {
            MBARRIER_WAIT_PARITY(sbar + st * 16 + 8, ph);
            P_LOAD_TILE(m0, n0, kt, st);
            CPASYNC_MBAR_ARRIVE_NOINC(sbar + st * 16);
            if (++st == S) { st = 0; ph ^= 1; }
        }
        asm volatile("cp.async.wait_all;\n" ::: "memory");
        return;
    }

    const int wm = wid >> 1, wn = wid & 1;
    uint32_t acc[4][8][2];
    #pragma unroll
    for (int f = 0; f < 4; ++f)
        #pragma unroll
        for (int n = 0; n < 8; ++n) { acc[f][n][0] = 0u; acc[f][n][1] = 0u; }

    int st = 0, ph = 0;
    for (int kt = 0; kt < KT; ++kt) {
        MBARRIER_WAIT_PARITY(sbar + st * 16, ph);
        const __half* sa = tiles + (size_t)st * STAGE_HALFS;
        const __half* sb = sa + 128 * PADK;

        uint32_t a0[4][4], b0[4][4];
        #pragma unroll
        for (int f = 0; f < 4; ++f) LDSM_A(a0[f], sa, f, 0);
        #pragma unroll
        for (int p = 0; p < 4; ++p) LDSM_B(b0[p], sb, p, 0);
        #pragma unroll
        for (int f = 0; f < 4; ++f)
            #pragma unroll
            for (int nf = 0; nf < 8; ++nf)
                HMMA_F16(acc[f][nf], a0[f],
                         b0[nf >> 1][(nf & 1) * 2 + 0],
                         b0[nf >> 1][(nf & 1) * 2 + 1]);

        uint32_t a1[4][4], b1[4][4];
        #pragma unroll
        for (int f = 0; f < 4; ++f) LDSM_A(a1[f], sa, f, 1);
        #pragma unroll
        for (int p = 0; p < 4; ++p) LDSM_B(b1[p], sb, p, 1);
        if (lane == 0) MBARRIER_ARRIVE(sbar + st * 16 + 8);   // release stage
        #pragma unroll
        for (int f = 0; f < 4; ++f)
            #pragma unroll
            for (int nf = 0; nf < 8; ++nf)
                HMMA_F16(acc[f][nf], a1[f],
                         b1[nf >> 1][(nf & 1) * 2 + 0],
                         b1[nf >> 1][(nf & 1) * 2 + 1]);
        if (++st == S) { st = 0; ph ^= 1; }
    }

    float t = __ldg(tempPtr);
    float tau = (t > 20.f) ? t : log1pf(expf(t));   // softplus
    #pragma unroll
    for (int f = 0; f < 4; ++f)
        #pragma unroll
        for (int nf = 0; nf < 8; ++nf) {
            int row = m0 + wm * 64 + f * 16 + (lane >> 2);
            int col = n0 + wn * 64 + nf * 8 + (lane & 3) * 2;
            #pragma unroll
            for (int hh = 0; hh < 2; ++hh) {
                int r = row + hh * 8;
                float2 d = __half22float2(*(__half2*)&acc[f][nf][hh]);
                float a0e = __expf(-tau * sqrtf(fmaxf(2.f - 2.f * d.x, 0.f)));
                float a1e = __expf(-tau * sqrtf(fmaxf(2.f - 2.f * d.y, 0.f)));
                *(__half2*)(outH + (size_t)r * P_DIM + col) =
                    __floats2half2_rn(a0e, a1e);
            }
        }
}

// ---------------------------------------------------------------------------
// GEMM2: f32 acc, 128 thr, 2 CTAs/SM (8 warps/SM => 256-reg SMSP budget),
// persistent, SELF-PRODUCED mbarrier pipeline: every warp issues its slice
// of stage s+3 after waiting empty[s+3] (count 4), full[s] signaled via
// per-thread cp.async.mbarrier.arrive.noinc (count 128). No __syncthreads
// in the mainloop -> warps skew up to ~1 chunk instead of exact rendezvous.
// ---------------------------------------------------------------------------
#define G2_TILES ((N_ROWS / 128) * (C_PAD / 128))   // 1024
#define G2_GRID  296                                 // 2 per SM * 148

__global__ void __launch_bounds__(128, 2) gemm2_persistent_kernel(
    const __half* __restrict__ A, const __half* __restrict__ B,
    float* __restrict__ outF)
{
    constexpr int KDIM = P_DIM;
    constexpr int KT = KDIM / 32;   // 64
    constexpr int S = G2_STAGES;    // 4
    extern __shared__ char smem[];
    const uint32_t sbar = smem_u32(smem);
    __half* tiles = (__half*)(smem + TILES_OFF);
    const int tid = threadIdx.x, wid = tid >> 5, lane = tid & 31;
    const int wm = wid >> 1, wn = wid & 1;

    if (tid == 0) {
        #pragma unroll
        for (int s = 0; s < S; ++s) {
            MBARRIER_INIT(sbar + s * 16, 128);     // full: all threads' cp.async
            MBARRIER_INIT(sbar + s * 16 + 8, 4);   // empty: 4 warps
        }
    }
    __syncthreads();

    const int t0 = blockIdx.x;
    const int ntiles = (G2_TILES - t0 + G2_GRID - 1) / G2_GRID;
    const int total_chunks = ntiles * KT;

    int lst = 0, lph = 1;   // load cursor
    int cst = 0, cph = 0;   // consume cursor

    // Prologue: fill first min(3, total) chunks (empty waits pass: parity 1)
    for (int c = 0; c < S - 1 && c < total_chunks; ++c) {
        MBARRIER_WAIT_PARITY(sbar + lst * 16 + 8, lph);
        int li = c >> 6, lkt = c & 63;
        int tt = t0 + li * G2_GRID;
        int gm = (tt >> 3) * 128, gn = (tt & 7) * 128;
        LOAD_TILE_MB(gm, gn, lkt, lst);
        CPASYNC_MBAR_ARRIVE_NOINC(sbar + lst * 16);
        if (++lst == S) { lst = 0; lph ^= 1; }
    }

    int ci = 0;   // global consume-chunk counter
    for (int i = 0; i < ntiles; ++i) {
        const int t = t0 + i * G2_GRID;
        const int m0 = (t >> 3) * 128, n0 = (t & 7) * 128;

        float acc[4][8][4];
        #pragma unroll
        for (int f = 0; f < 4; ++f)
            #pragma unroll
            for (int n = 0; n < 8; ++n)
                #pragma unroll
                for (int k = 0; k < 4; ++k) acc[f][n][k] = 0.f;

        for (int kt = 0; kt < KT; ++kt) {
            // Issue loads for chunk ci+3 (burst-first order)
            const int c = ci + S - 1;
            if (c < total_chunks) {
                MBARRIER_WAIT_PARITY(sbar + lst * 16 + 8, lph);
                int li = c >> 6, lkt = c & 63;
                int tt = t0 + li * G2_GRID;
                int gm = (tt >> 3) * 128, gn = (tt & 7) * 128;
                LOAD_TILE_MB(gm, gn, lkt, lst);
                CPASYNC_MBAR_ARRIVE_NOINC(sbar + lst * 16);
                if (++lst == S) { lst = 0; lph ^= 1; }
            }

            // Consume chunk ci
            MBARRIER_WAIT_PARITY(sbar + cst * 16, cph);
            const __half* sa = tiles + (size_t)cst * STAGE_HALFS;
            const __half* sb = sa + 128 * PADK;

            uint32_t a0[4][4], b0[4][4];
            #pragma unroll
            for (int f = 0; f < 4; ++f) LDSM_A(a0[f], sa, f, 0);
            #pragma unroll
            for (int p = 0; p < 4; ++p) LDSM_B(b0[p], sb, p, 0);
            #pragma unroll
            for (int f = 0; f < 4; ++f)
                #pragma unroll
                for (int nf = 0; nf < 8; ++nf)
                    HMMA_F32(acc[f][nf], a0[f],
                             b0[nf >> 1][(nf & 1) * 2 + 0],
                             b0[nf >> 1][(nf & 1) * 2 + 1]);

            uint32_t a1[4][4], b1[4][4];
            #pragma unroll
            for (int f = 0; f < 4; ++f) LDSM_A(a1[f], sa, f, 1);
            #pragma unroll
            for (int p = 0; p < 4; ++p) LDSM_B(b1[p], sb, p, 1);
            if (lane == 0) MBARRIER_ARRIVE(sbar + cst * 16 + 8);  // release
            #pragma unroll
            for (int f = 0; f < 4; ++f)
                #pragma unroll
                for (int nf = 0; nf < 8; ++nf)
                    HMMA_F32(acc[f][nf], a1[f],
                             b1[nf >> 1][(nf & 1) * 2 + 0],
                             b1[nf >> 1][(nf & 1) * 2 + 1]);
            if (++cst == S) { cst = 0; cph ^= 1; }
            ++ci;
        }

        // Epilogue (next tile's first chunks already in flight)
        #pragma unroll
        for (int f = 0; f < 4; ++f)
            #pragma unroll
            for (int nf = 0; nf < 8; ++nf) {
                int row = m0 + wm * 64 + f * 16 + (lane >> 2);
                int col = n0 + wn * 64 + nf * 8 + (lane & 3) * 2;
                if (col < C_DIM) {   // even cols; pair never straddles C_DIM
                    #pragma unroll
                    for (int hh = 0; hh < 2; ++hh) {
                        int r = row + hh * 8;
                        float2 v = make_float2(acc[f][nf][hh * 2 + 0],
                                               acc[f][nf][hh * 2 + 1]);
                        *(float2*)(outF + (size_t)r * C_DIM + col) = v;
                    }
                }
            }
    }
}

// ---------------------------------------------------------------------------
// kernel_launch: 4 launches, all graph-capturable, no allocations.
// ---------------------------------------------------------------------------
extern "C" void kernel_launch(void* const* d_in, const int* in_sizes, int n_in,
                              void* d_out, int out_size) {
    const float* h    = (const float*)d_in[0];
    const float* prot = (const float*)d_in[1];
    const float* pc   = (const float*)d_in[2];
    const float* temp = (const float*)d_in[3];
    float* out = (float*)d_out;

    __half *hn = nullptr, *pn = nullptr, *act = nullptr, *pct = nullptr;
    cudaGetSymbolAddress((void**)&hn,  g_hn);
    cudaGetSymbolAddress((void**)&pn,  g_pn);
    cudaGetSymbolAddress((void**)&act, g_act);
    cudaGetSymbolAddress((void**)&pct, g_pct);

    cudaFuncSetAttribute(gemm_act_kernel,
                         cudaFuncAttributeMaxDynamicSharedMemorySize,
                         (int)G1_SMEM);
    cudaFuncSetAttribute(gemm2_persistent_kernel,
                         cudaFuncAttributeMaxDynamicSharedMemorySize,
                         (int)G2_SMEM);

    // 1) normalize h and prototypes -> fp16 (single launch, vectorized)
    normalize_rows_kernel<<<N_ROWS + P_DIM, 256>>>(h, prot);
    // 2) transpose + pad prototype_class -> fp16 [C_PAD, P]
    transpose_pc_kernel<<<dim3(P_DIM / 32, C_PAD / 32), dim3(32, 8)>>>(pc);
    // 3) GEMM1 (f16 accum, warp-specialized, 3 CTAs/SM) + dist/exp epilogue
    gemm_act_kernel
        <<<dim3(P_DIM / 128, N_ROWS / 128), 160, G1_SMEM>>>(hn, pn, act, temp);
    // 4) GEMM2 (f32 accum, self-produced mbarrier pipeline, 2 CTAs/SM)
    gemm2_persistent_kernel<<<G2_GRID, 128, G2_SMEM>>>(act, pct, out);
}